// round 5
// baseline (speedup 1.0000x reference)
#include <cuda_runtime.h>

#define N_NODES 100000
#define N_EDGES 1000000
#define D 64

// 25.6 MB scratch: agg[n] = features[n] + sum_{e: dst=n} w_e * features[src_e]
__device__ __align__(16) float g_agg[N_NODES * D];

// ---------------------------------------------------------------------------
// Kernel 1: agg = features  (residual folded into the scatter accumulator)
// ---------------------------------------------------------------------------
__global__ void init_kernel(const float* __restrict__ feat) {
    int i = blockIdx.x * blockDim.x + threadIdx.x;
    const int n4 = N_NODES * D / 4;
    if (i < n4) {
        reinterpret_cast<float4*>(g_agg)[i] =
            reinterpret_cast<const float4*>(feat)[i];
    }
}

// ---------------------------------------------------------------------------
// Kernel 2: scatter-add messages. 16 lanes per edge, float4 per lane.
// edge_index arrives as int32 (harness downcasts int64 inputs).
// ---------------------------------------------------------------------------
__global__ void scatter_kernel(const float* __restrict__ feat,
                               const int* __restrict__ ei,
                               const float* __restrict__ ew) {
    int t = blockIdx.x * blockDim.x + threadIdx.x;
    int e = t >> 4;
    int c = t & 15;
    if (e >= N_EDGES) return;

    int src = ei[e];            // edge_index[0][e]
    int dst = ei[N_EDGES + e];  // edge_index[1][e]
    // defense-in-depth: clamp so a misinterpreted index can't crash
    src = min(max(src, 0), N_NODES - 1);
    dst = min(max(dst, 0), N_NODES - 1);
    float w = ew[e];

    float4 v = *reinterpret_cast<const float4*>(feat + (long long)src * D + c * 4);
    v.x *= w; v.y *= w; v.z *= w; v.w *= w;

    float* p = g_agg + (long long)dst * D + c * 4;
    atomicAdd(p + 0, v.x);
    atomicAdd(p + 1, v.y);
    atomicAdd(p + 2, v.z);
    atomicAdd(p + 3, v.w);
}

// ---------------------------------------------------------------------------
// Kernel 3: out = agg @ W^T + b.
// Block: 256 threads, 64-node tile. Thread (tx,ty) computes 4 nodes x 4 outs.
// ---------------------------------------------------------------------------
__global__ void gemm_kernel(const float* __restrict__ W,
                            const float* __restrict__ b,
                            float* __restrict__ out) {
    __shared__ float As[64 * 64];   // [node][k]
    __shared__ float Wt[64 * 64];   // [k][j]
    __shared__ float bs[64];

    int tid = threadIdx.x;          // 0..255
    int n0  = blockIdx.x * 64;

    #pragma unroll
    for (int i = tid; i < 4096; i += 256) {
        int j = i & 63;
        int k = i >> 6;
        Wt[k * 64 + j] = W[j * 64 + k];
    }
    if (tid < 64) bs[tid] = b[tid];

    #pragma unroll
    for (int r = 0; r < 4; r++) {
        int i4   = tid + r * 256;        // 0..1023
        int row  = i4 >> 4;              // 0..63
        int col4 = i4 & 15;              // 0..15
        int node = n0 + row;
        int src  = (node < N_NODES) ? node : (N_NODES - 1);
        reinterpret_cast<float4*>(As)[i4] =
            reinterpret_cast<const float4*>(g_agg + (long long)src * D)[col4];
    }
    __syncthreads();

    int tx = tid & 15;   // output group: j0 = tx*4
    int ty = tid >> 4;   // node group:   n  = ty*4 + i

    float acc[4][4];
    #pragma unroll
    for (int i = 0; i < 4; i++)
        #pragma unroll
        for (int j = 0; j < 4; j++)
            acc[i][j] = 0.0f;

    #pragma unroll
    for (int k = 0; k < 64; k += 4) {
        float4 a[4];
        float4 w[4];
        #pragma unroll
        for (int i = 0; i < 4; i++)
            a[i] = *reinterpret_cast<const float4*>(&As[(ty * 4 + i) * 64 + k]);
        #pragma unroll
        for (int kk = 0; kk < 4; kk++)
            w[kk] = *reinterpret_cast<const float4*>(&Wt[(k + kk) * 64 + tx * 4]);

        #pragma unroll
        for (int i = 0; i < 4; i++) {
            acc[i][0] += a[i].x * w[0].x; acc[i][1] += a[i].x * w[0].y;
            acc[i][2] += a[i].x * w[0].z; acc[i][3] += a[i].x * w[0].w;

            acc[i][0] += a[i].y * w[1].x; acc[i][1] += a[i].y * w[1].y;
            acc[i][2] += a[i].y * w[1].z; acc[i][3] += a[i].y * w[1].w;

            acc[i][0] += a[i].z * w[2].x; acc[i][1] += a[i].z * w[2].y;
            acc[i][2] += a[i].z * w[2].z; acc[i][3] += a[i].z * w[2].w;

            acc[i][0] += a[i].w * w[3].x; acc[i][1] += a[i].w * w[3].y;
            acc[i][2] += a[i].w * w[3].z; acc[i][3] += a[i].w * w[3].w;
        }
    }

    float4 bias = *reinterpret_cast<const float4*>(&bs[tx * 4]);
    #pragma unroll
    for (int i = 0; i < 4; i++) {
        int node = n0 + ty * 4 + i;
        if (node < N_NODES) {
            float4 o;
            o.x = acc[i][0] + bias.x;
            o.y = acc[i][1] + bias.y;
            o.z = acc[i][2] + bias.z;
            o.w = acc[i][3] + bias.w;
            *reinterpret_cast<float4*>(out + (long long)node * D + tx * 4) = o;
        }
    }
}

extern "C" void kernel_launch(void* const* d_in, const int* in_sizes, int n_in,
                              void* d_out, int out_size) {
    // Bind inputs by element count — robust to metadata ordering.
    // features: 6,400,000 f32 | edge_index: 2,000,000 i32 |
    // edge_weight: 1,000,000 f32 | W: 4096 f32 | b: 64 f32
    const float* feat = nullptr;
    const int*   ei   = nullptr;
    const float* ew   = nullptr;
    const float* W    = nullptr;
    const float* b    = nullptr;

    for (int i = 0; i < n_in; i++) {
        switch (in_sizes[i]) {
            case N_NODES * D:   feat = (const float*)d_in[i]; break;
            case 2 * N_EDGES:   ei   = (const int*)d_in[i];   break;
            case N_EDGES:       ew   = (const float*)d_in[i]; break;
            case D * D:         W    = (const float*)d_in[i]; break;
            case D:             b    = (const float*)d_in[i]; break;
            default: break;
        }
    }

    float* out = (float*)d_out;

    init_kernel<<<(N_NODES * D / 4 + 255) / 256, 256>>>(feat);
    scatter_kernel<<<(N_EDGES * 16 + 255) / 256, 256>>>(feat, ei, ew);
    gemm_kernel<<<(N_NODES + 63) / 64, 256>>>(W, b, out);
}

// round 6
// speedup vs baseline: 1.8914x; 1.8914x over previous
#include <cuda_runtime.h>

#define N_NODES 100000
#define N_EDGES 1000000
#define D 64

// 25.6 MB scratch: agg[n] = features[n] + sum_{e: dst=n} w_e * features[src_e]
__device__ __align__(16) float g_agg[N_NODES * D];

// ---------------------------------------------------------------------------
// Kernel 1: agg = features  (residual folded into the scatter accumulator)
// ---------------------------------------------------------------------------
__global__ void init_kernel(const float* __restrict__ feat) {
    int i = blockIdx.x * blockDim.x + threadIdx.x;
    const int n4 = N_NODES * D / 4;
    if (i < n4) {
        reinterpret_cast<float4*>(g_agg)[i] =
            reinterpret_cast<const float4*>(feat)[i];
    }
}

// ---------------------------------------------------------------------------
// Kernel 2: scatter-add. 16 lanes/edge, one float4 gather + one RED.128 each.
// ---------------------------------------------------------------------------
__global__ void scatter_kernel(const float* __restrict__ feat,
                               const int* __restrict__ ei,
                               const float* __restrict__ ew) {
    int t = blockIdx.x * blockDim.x + threadIdx.x;
    int e = t >> 4;
    int c = t & 15;
    if (e >= N_EDGES) return;

    int src = ei[e];            // edge_index[0][e]
    int dst = ei[N_EDGES + e];  // edge_index[1][e]
    src = min(max(src, 0), N_NODES - 1);
    dst = min(max(dst, 0), N_NODES - 1);
    float w = ew[e];

    float4 v = *reinterpret_cast<const float4*>(feat + (long long)src * D + c * 4);
    v.x *= w; v.y *= w; v.z *= w; v.w *= w;

    float* p = g_agg + (long long)dst * D + c * 4;
    asm volatile("red.global.add.v4.f32 [%0], {%1,%2,%3,%4};"
                 :: "l"(p), "f"(v.x), "f"(v.y), "f"(v.z), "f"(v.w)
                 : "memory");
}

// ---------------------------------------------------------------------------
// Kernel 3: out = agg @ W^T + b, using packed fma.rn.f32x2.
//
// Shared layout engineered so both f32x2 operands are natural register pairs:
//   Adup[k][2n..2n+1] = agg value DUPLICATED  -> LDS.64 yields (a,a)
//   Wt[k][j]          = W transposed          -> LDS.128 yields (w0,w1),(w2,w3)
// XOR swizzles keep the transpose fills and the k-loop reads conflict-free.
// Thread (tx,ty): 4 nodes (ty*4+i) x 4 outputs (tx*4..tx*4+3) as f32x2 pairs.
// ---------------------------------------------------------------------------
__global__ void gemm_kernel(const float* __restrict__ W,
                            const float* __restrict__ b,
                            float* __restrict__ out) {
    __shared__ float Adup[64 * 128];   // 32 KB: [k][dup-node], swizzled
    __shared__ float Wt[64 * 64];      // 16 KB: [k][j], swizzled

    int tid = threadIdx.x;             // 0..255
    int n0  = blockIdx.x * 64;

    // ---- Fill Wt (coalesced LDG, swizzled STS) ----
    // W[j][k]: lane-fast index is k. Write Wt[k][j ^ (4*(k&15))].
    #pragma unroll
    for (int i = tid; i < 4096; i += 256) {
        int j = i >> 6;            // W row (output)
        int k = i & 63;            // W col (input)  -> coalesced read
        int col = j ^ (4 * (k & 15));
        Wt[k * 64 + col] = W[i];
    }

    // ---- Fill Adup (coalesced LDG of 4 k's per node, duplicated STS.64) ----
    #pragma unroll
    for (int r = 0; r < 4; r++) {
        int i4  = tid + r * 256;       // 0..1023
        int row = i4 >> 4;             // node-in-tile 0..63
        int kg  = i4 & 15;             // k-group 0..15
        int node = n0 + row;
        int src  = (node < N_NODES) ? node : (N_NODES - 1);
        float4 v = *reinterpret_cast<const float4*>(g_agg + (long long)src * D + kg * 4);
        int col = (2 * row) ^ (2 * kg);    // swizzle g(k)=2*(k>>2)
        #pragma unroll
        for (int j = 0; j < 4; j++) {
            int k = kg * 4 + j;
            float f = (&v.x)[j];
            *reinterpret_cast<float2*>(&Adup[k * 128 + col]) = make_float2(f, f);
        }
    }
    __syncthreads();

    int tx = tid & 15;   // output group: j0 = tx*4
    int ty = tid >> 4;   // node group:   n  = ty*4 + i

    unsigned long long acc01[4] = {0ull, 0ull, 0ull, 0ull};
    unsigned long long acc23[4] = {0ull, 0ull, 0ull, 0ull};

    #pragma unroll
    for (int k = 0; k < 64; k++) {
        int wcol = (tx * 4) ^ (4 * (k & 15));
        double2 wq = *reinterpret_cast<const double2*>(&Wt[k * 64 + wcol]);
        unsigned long long w01 = __double_as_longlong(wq.x);
        unsigned long long w23 = __double_as_longlong(wq.y);
        int g = 2 * (k >> 2);
        #pragma unroll
        for (int i = 0; i < 4; i++) {
            int n = ty * 4 + i;
            unsigned long long aa =
                *reinterpret_cast<const unsigned long long*>(&Adup[k * 128 + ((2 * n) ^ g)]);
            asm("fma.rn.f32x2 %0, %1, %2, %0;" : "+l"(acc01[i]) : "l"(aa), "l"(w01));
            asm("fma.rn.f32x2 %0, %1, %2, %0;" : "+l"(acc23[i]) : "l"(aa), "l"(w23));
        }
    }

    // bias pairs straight from global (L2-resident, read once per thread)
    double2 bq = *reinterpret_cast<const double2*>(b + tx * 4);
    unsigned long long b01 = __double_as_longlong(bq.x);
    unsigned long long b23 = __double_as_longlong(bq.y);

    #pragma unroll
    for (int i = 0; i < 4; i++) {
        int node = n0 + ty * 4 + i;
        if (node < N_NODES) {
            unsigned long long o01, o23;
            asm("add.rn.f32x2 %0, %1, %2;" : "=l"(o01) : "l"(acc01[i]), "l"(b01));
            asm("add.rn.f32x2 %0, %1, %2;" : "=l"(o23) : "l"(acc23[i]), "l"(b23));
            double2 o;
            o.x = __longlong_as_double(o01);
            o.y = __longlong_as_double(o23);
            *reinterpret_cast<double2*>(out + (long long)node * D + tx * 4) = o;
        }
    }
}

extern "C" void kernel_launch(void* const* d_in, const int* in_sizes, int n_in,
                              void* d_out, int out_size) {
    // Bind inputs by element count — robust to metadata ordering.
    const float* feat = nullptr;
    const int*   ei   = nullptr;
    const float* ew   = nullptr;
    const float* W    = nullptr;
    const float* b    = nullptr;

    for (int i = 0; i < n_in; i++) {
        switch (in_sizes[i]) {
            case N_NODES * D:   feat = (const float*)d_in[i]; break;
            case 2 * N_EDGES:   ei   = (const int*)d_in[i];   break;
            case N_EDGES:       ew   = (const float*)d_in[i]; break;
            case D * D:         W    = (const float*)d_in[i]; break;
            case D:             b    = (const float*)d_in[i]; break;
            default: break;
        }
    }

    float* out = (float*)d_out;

    init_kernel<<<(N_NODES * D / 4 + 255) / 256, 256>>>(feat);
    scatter_kernel<<<(N_EDGES * 16 + 255) / 256, 256>>>(feat, ei, ew);
    gemm_kernel<<<(N_NODES + 63) / 64, 256>>>(W, b, out);
}

// round 7
// speedup vs baseline: 1.9010x; 1.0051x over previous
#include <cuda_runtime.h>

#define N_NODES 100000
#define N_EDGES 1000000
#define D 64

#define HIST_BLOCKS ((N_NODES + 255) / 256)   // 391

// Scratch (static — no allocs allowed)
__device__ __align__(16) float g_agg[N_NODES * D];          // 25.6 MB
__device__ int g_deg[N_NODES];
__device__ int g_off[N_NODES];
__device__ int g_cur[N_NODES];
__device__ unsigned long long g_csr[N_EDGES];               // packed (w<<32 | src)
__device__ int g_bsum[HIST_BLOCKS];
__device__ int g_bpre[512];

// ---------------------------------------------------------------------------
// CSR build step 1: zero degree counters
// ---------------------------------------------------------------------------
__global__ void zero_deg_kernel() {
    int i = blockIdx.x * blockDim.x + threadIdx.x;
    if (i < N_NODES) g_deg[i] = 0;
}

// CSR build step 2: histogram of destination nodes
__global__ void hist_kernel(const int* __restrict__ ei) {
    int e = blockIdx.x * blockDim.x + threadIdx.x;
    if (e >= N_EDGES) return;
    int dst = ei[N_EDGES + e];
    dst = min(max(dst, 0), N_NODES - 1);
    atomicAdd(&g_deg[dst], 1);
}

// block-exclusive scan helper (256 threads)
__device__ __forceinline__ int block_excl_scan_256(int v, int tid, int* wsum) {
    int lane = tid & 31, wid = tid >> 5;
    int inc = v;
    #pragma unroll
    for (int d = 1; d < 32; d <<= 1) {
        int t = __shfl_up_sync(0xffffffffu, inc, d);
        if (lane >= d) inc += t;
    }
    if (lane == 31) wsum[wid] = inc;
    __syncthreads();
    if (tid < 8) {
        int s = wsum[tid];
        #pragma unroll
        for (int d = 1; d < 8; d <<= 1) {
            int t = __shfl_up_sync(0xffu, s, d);
            if (tid >= d) s += t;
        }
        wsum[tid] = s;
    }
    __syncthreads();
    return inc - v + (wid > 0 ? wsum[wid - 1] : 0);
}

// CSR build step 3: per-block degree sums
__global__ void partial_kernel() {
    __shared__ int wsum[8];
    int tid = threadIdx.x;
    int i = blockIdx.x * 256 + tid;
    int v = (i < N_NODES) ? g_deg[i] : 0;
    int excl = block_excl_scan_256(v, tid, wsum);
    if (tid == 255) g_bsum[blockIdx.x] = excl + v;   // block total
}

// CSR build step 4: scan of block sums (single block, 512 threads)
__global__ void scanb_kernel() {
    __shared__ int wsum[16];
    int tid = threadIdx.x;
    int lane = tid & 31, wid = tid >> 5;
    int v = (tid < HIST_BLOCKS) ? g_bsum[tid] : 0;
    int inc = v;
    #pragma unroll
    for (int d = 1; d < 32; d <<= 1) {
        int t = __shfl_up_sync(0xffffffffu, inc, d);
        if (lane >= d) inc += t;
    }
    if (lane == 31) wsum[wid] = inc;
    __syncthreads();
    if (tid < 16) {
        int s = wsum[tid];
        #pragma unroll
        for (int d = 1; d < 16; d <<= 1) {
            int t = __shfl_up_sync(0xffffu, s, d);
            if (tid >= d) s += t;
        }
        wsum[tid] = s;
    }
    __syncthreads();
    g_bpre[tid] = inc - v + (wid > 0 ? wsum[wid - 1] : 0);
}

// CSR build step 5: write offsets + cursors
__global__ void offsets_kernel() {
    __shared__ int wsum[8];
    int tid = threadIdx.x;
    int i = blockIdx.x * 256 + tid;
    int v = (i < N_NODES) ? g_deg[i] : 0;
    int excl = block_excl_scan_256(v, tid, wsum);
    if (i < N_NODES) {
        int off = g_bpre[blockIdx.x] + excl;
        g_off[i] = off;
        g_cur[i] = off;
    }
}

// CSR build step 6: fill edge lists with packed (weight, src)
__global__ void fill_kernel(const int* __restrict__ ei,
                            const float* __restrict__ ew) {
    int e = blockIdx.x * blockDim.x + threadIdx.x;
    if (e >= N_EDGES) return;
    int dst = ei[N_EDGES + e];
    dst = min(max(dst, 0), N_NODES - 1);
    int src = ei[e];
    src = min(max(src, 0), N_NODES - 1);
    float w = ew[e];
    int pos = atomicAdd(&g_cur[dst], 1);
    g_csr[pos] = ((unsigned long long)__float_as_uint(w) << 32) | (unsigned)src;
}

// ---------------------------------------------------------------------------
// Aggregate: one warp per node. agg[n] = feat[n] + sum_e w_e * feat[src_e].
// Pure gathers + one plain store — zero float atomics.
// ---------------------------------------------------------------------------
__global__ void agg_kernel(const float* __restrict__ feat) {
    int n = blockIdx.x * 8 + (threadIdx.x >> 5);
    if (n >= N_NODES) return;
    int lane = threadIdx.x & 31;

    int beg = g_off[n];
    int end = (n == N_NODES - 1) ? N_EDGES : g_off[n + 1];

    float2 acc = *reinterpret_cast<const float2*>(feat + (long long)n * D + lane * 2);

    int i = beg;
    // software-pipelined by 2 for MLP
    if (i < end) {
        unsigned long long p = g_csr[i];
        while (i + 1 < end) {
            unsigned long long pn = g_csr[i + 1];
            int src = (int)(unsigned)(p & 0xffffffffu);
            float w = __uint_as_float((unsigned)(p >> 32));
            float2 v = *reinterpret_cast<const float2*>(feat + (long long)src * D + lane * 2);
            acc.x += w * v.x; acc.y += w * v.y;
            p = pn;
            i++;
        }
        int src = (int)(unsigned)(p & 0xffffffffu);
        float w = __uint_as_float((unsigned)(p >> 32));
        float2 v = *reinterpret_cast<const float2*>(feat + (long long)src * D + lane * 2);
        acc.x += w * v.x; acc.y += w * v.y;
    }

    *reinterpret_cast<float2*>(g_agg + (long long)n * D + lane * 2) = acc;
}

// ---------------------------------------------------------------------------
// GEMM: out = agg @ W^T + b, packed fma.rn.f32x2 (unchanged from R6).
// ---------------------------------------------------------------------------
__global__ void gemm_kernel(const float* __restrict__ W,
                            const float* __restrict__ b,
                            float* __restrict__ out) {
    __shared__ float Adup[64 * 128];   // 32 KB: [k][dup-node], swizzled
    __shared__ float Wt[64 * 64];      // 16 KB: [k][j], swizzled

    int tid = threadIdx.x;             // 0..255
    int n0  = blockIdx.x * 64;

    #pragma unroll
    for (int i = tid; i < 4096; i += 256) {
        int j = i >> 6;
        int k = i & 63;
        int col = j ^ (4 * (k & 15));
        Wt[k * 64 + col] = W[i];
    }

    #pragma unroll
    for (int r = 0; r < 4; r++) {
        int i4  = tid + r * 256;
        int row = i4 >> 4;
        int kg  = i4 & 15;
        int node = n0 + row;
        int src  = (node < N_NODES) ? node : (N_NODES - 1);
        float4 v = *reinterpret_cast<const float4*>(g_agg + (long long)src * D + kg * 4);
        int col = (2 * row) ^ (2 * kg);
        #pragma unroll
        for (int j = 0; j < 4; j++) {
            int k = kg * 4 + j;
            float f = (&v.x)[j];
            *reinterpret_cast<float2*>(&Adup[k * 128 + col]) = make_float2(f, f);
        }
    }
    __syncthreads();

    int tx = tid & 15;
    int ty = tid >> 4;

    unsigned long long acc01[4] = {0ull, 0ull, 0ull, 0ull};
    unsigned long long acc23[4] = {0ull, 0ull, 0ull, 0ull};

    #pragma unroll
    for (int k = 0; k < 64; k++) {
        int wcol = (tx * 4) ^ (4 * (k & 15));
        double2 wq = *reinterpret_cast<const double2*>(&Wt[k * 64 + wcol]);
        unsigned long long w01 = __double_as_longlong(wq.x);
        unsigned long long w23 = __double_as_longlong(wq.y);
        int g = 2 * (k >> 2);
        #pragma unroll
        for (int i = 0; i < 4; i++) {
            int n = ty * 4 + i;
            unsigned long long aa =
                *reinterpret_cast<const unsigned long long*>(&Adup[k * 128 + ((2 * n) ^ g)]);
            asm("fma.rn.f32x2 %0, %1, %2, %0;" : "+l"(acc01[i]) : "l"(aa), "l"(w01));
            asm("fma.rn.f32x2 %0, %1, %2, %0;" : "+l"(acc23[i]) : "l"(aa), "l"(w23));
        }
    }

    double2 bq = *reinterpret_cast<const double2*>(b + tx * 4);
    unsigned long long b01 = __double_as_longlong(bq.x);
    unsigned long long b23 = __double_as_longlong(bq.y);

    #pragma unroll
    for (int i = 0; i < 4; i++) {
        int node = n0 + ty * 4 + i;
        if (node < N_NODES) {
            unsigned long long o01, o23;
            asm("add.rn.f32x2 %0, %1, %2;" : "=l"(o01) : "l"(acc01[i]), "l"(b01));
            asm("add.rn.f32x2 %0, %1, %2;" : "=l"(o23) : "l"(acc23[i]), "l"(b23));
            double2 o;
            o.x = __longlong_as_double(o01);
            o.y = __longlong_as_double(o23);
            *reinterpret_cast<double2*>(out + (long long)node * D + tx * 4) = o;
        }
    }
}

extern "C" void kernel_launch(void* const* d_in, const int* in_sizes, int n_in,
                              void* d_out, int out_size) {
    const float* feat = nullptr;
    const int*   ei   = nullptr;
    const float* ew   = nullptr;
    const float* W    = nullptr;
    const float* b    = nullptr;

    for (int i = 0; i < n_in; i++) {
        switch (in_sizes[i]) {
            case N_NODES * D:   feat = (const float*)d_in[i]; break;
            case 2 * N_EDGES:   ei   = (const int*)d_in[i];   break;
            case N_EDGES:       ew   = (const float*)d_in[i]; break;
            case D * D:         W    = (const float*)d_in[i]; break;
            case D:             b    = (const float*)d_in[i]; break;
            default: break;
        }
    }

    float* out = (float*)d_out;

    zero_deg_kernel<<<HIST_BLOCKS, 256>>>();
    hist_kernel<<<(N_EDGES + 255) / 256, 256>>>(ei);
    partial_kernel<<<HIST_BLOCKS, 256>>>();
    scanb_kernel<<<1, 512>>>();
    offsets_kernel<<<HIST_BLOCKS, 256>>>();
    fill_kernel<<<(N_EDGES + 255) / 256, 256>>>(ei, ew);
    agg_kernel<<<(N_NODES + 7) / 8, 256>>>(feat);
    gemm_kernel<<<(N_NODES + 63) / 64, 256>>>(W, b, out);
}